// round 17
// baseline (speedup 1.0000x reference)
#include <cuda_runtime.h>

#define Bb 4
#define Ss 1024
#define Dd 32
#define Hh 32
#define NBLK 128           // 4 batches x 32 row-slices
#define NTHR 256           // 8 warps; warp w handles rows 4w..4w+3
#define WPAD 33            // padded stride for scalar-read arrays
#define WPAD4 36           // padded stride (floats) for f4-read weight arrays

// ping-pong accumulators: g_acc[parity][b][0][h]=S, [1][h]=SV  (zero-init)
__device__ float g_acc[2][Bb][2][Hh];
__device__ unsigned g_ticket[Bb * 32];   // +32/call each; epoch = ticket>>5
__device__ unsigned g_done  [Bb * 32];   // +32/call each

__global__ void __launch_bounds__(NTHR, 1) foaa_fused(
    const float* __restrict__ x,
    const float* __restrict__ Wk, const float* __restrict__ bk,
    const float* __restrict__ Wv, const float* __restrict__ bv,
    const float* __restrict__ Wo, const float* __restrict__ bo,
    float* __restrict__ out)
{
    const int b     = blockIdx.x >> 5;
    const int slice = blockIdx.x & 31;
    const int tid   = threadIdx.x;
    const int w     = tid >> 5;
    const int lane  = tid & 31;

    __shared__ __align__(16) float wk_s[Hh * WPAD4];
    __shared__ __align__(16) float wv_s[Hh * WPAD4];
    __shared__ float wo_s[Dd * WPAD];
    __shared__ float sred[8 * WPAD], svred[8 * WPAD];
    __shared__ float c_s[Hh];
    __shared__ __align__(16) float y[Dd];
    __shared__ float s_bo[Dd], s_bv[Dd];
    __shared__ unsigned s_epoch;

    // ---- Ticket first: learn this call's epoch (latency overlaps all of
    //      stage 1). Exactly 32 arrivals per batch counter per call. ----
    if (tid == 0) {
        unsigned t = atomicAdd(&g_ticket[b * 32], 1u);
        s_epoch = t >> 5;
    }

    // ---- Preamble: weights -> smem (coalesced f4; padded scatter) ----
    {
        float4 vk = ((const float4*)Wk)[tid];
        float4 vv = ((const float4*)Wv)[tid];
        float4 vo = ((const float4*)Wo)[tid];
        int e = tid * 4, r = e >> 5, c0 = e & 31;
        *(float4*)&wk_s[r * WPAD4 + c0] = vk;
        *(float4*)&wv_s[r * WPAD4 + c0] = vv;
        wo_s[r * WPAD + c0 + 0] = vo.x;
        wo_s[r * WPAD + c0 + 1] = vo.y;
        wo_s[r * WPAD + c0 + 2] = vo.z;
        wo_s[r * WPAD + c0 + 3] = vo.w;
    }
    if (tid < 8)       ((float4*)s_bo)[tid]     = ((const float4*)bo)[tid];
    else if (tid < 16) ((float4*)s_bv)[tid - 8] = ((const float4*)bv)[tid - 8];
    __syncthreads();

    // ---- Per-lane head weights into registers (f4 LDS, conflict-free) ----
    float4 wk4[8], wv4[8];
    #pragma unroll
    for (int q = 0; q < 8; q++) {
        wk4[q] = *(const float4*)&wk_s[lane * WPAD4 + 4 * q];
        wv4[q] = *(const float4*)&wv_s[lane * WPAD4 + 4 * q];
    }

    // ---- Stage 1: warp w handles rows 4w..4w+3; lane = head.
    //      x read as uniform-broadcast LDG.128 (1 line/load, independent).
    const float4* xr = (const float4*)
        (x + ((size_t)b * Ss + slice * 32 + w * 4) * Dd);

    float s = 0.0f, sv = 0.0f;
    #pragma unroll
    for (int rr = 0; rr < 4; rr++) {
        float kp0 = 0.f, kp1 = 0.f, vp0 = 0.f, vp1 = 0.f;
        #pragma unroll
        for (int q = 0; q < 8; q += 2) {
            float4 a  = xr[rr * 8 + q];
            float4 bq = xr[rr * 8 + q + 1];
            kp0 = fmaf(a.x,  wk4[q].x,   kp0); kp0 = fmaf(a.y,  wk4[q].y,   kp0);
            kp0 = fmaf(a.z,  wk4[q].z,   kp0); kp0 = fmaf(a.w,  wk4[q].w,   kp0);
            vp0 = fmaf(a.x,  wv4[q].x,   vp0); vp0 = fmaf(a.y,  wv4[q].y,   vp0);
            vp0 = fmaf(a.z,  wv4[q].z,   vp0); vp0 = fmaf(a.w,  wv4[q].w,   vp0);
            kp1 = fmaf(bq.x, wk4[q+1].x, kp1); kp1 = fmaf(bq.y, wk4[q+1].y, kp1);
            kp1 = fmaf(bq.z, wk4[q+1].z, kp1); kp1 = fmaf(bq.w, wk4[q+1].w, kp1);
            vp1 = fmaf(bq.x, wv4[q+1].x, vp1); vp1 = fmaf(bq.y, wv4[q+1].y, vp1);
            vp1 = fmaf(bq.z, wv4[q+1].z, vp1); vp1 = fmaf(bq.w, wv4[q+1].w, vp1);
        }
        float e = __expf(kp0 + kp1);       // bk cancels in softmax
        s += e;
        sv = fmaf(e, vp0 + vp1, sv);       // bv added in epilogue
    }
    sred [w * WPAD + lane] = s;
    svred[w * WPAD + lane] = sv;
    __syncthreads();

    const unsigned epoch = s_epoch;
    const unsigned par   = epoch & 1u;

    // ---- Warp 0: block column-sum (fixed order), then RED.ADD into the
    //      per-batch L2 accumulator (fire-and-forget, no return) ----
    if (w == 0) {
        float S = 0.f, SV = 0.f;
        #pragma unroll
        for (int k2 = 0; k2 < 8; k2++) {
            S  += sred [k2 * WPAD + lane];
            SV += svred[k2 * WPAD + lane];
        }
        atomicAdd(&g_acc[par][b][0][lane], S);    // RED.ADD.F32
        atomicAdd(&g_acc[par][b][1][lane], SV);
    }
    __syncthreads();   // REDs above ordered before tid0's release-add

    // ---- Per-batch barrier: release-add arrive + acquire poll ----
    if (tid == 0) {
        unsigned c0;
        asm volatile("atom.release.gpu.global.add.u32 %0, [%1], 1;"
                     : "=r"(c0) : "l"(&g_done[b * 32]) : "memory");
        (void)c0;
        unsigned target = (epoch + 1u) * 32u;
        unsigned vcur;
        do {
            asm volatile("ld.acquire.gpu.u32 %0, [%1];"
                         : "=r"(vcur) : "l"(&g_done[b * 32]) : "memory");
        } while (vcur < target);
    }
    __syncthreads();

    // ---- Tail: 2x128B ldcg, divide, 32x32 matvec, 4KB broadcast store ----
    if (w == 0) {
        float S  = __ldcg(&g_acc[par][b][0][lane]);
        float SV = __ldcg(&g_acc[par][b][1][lane]);
        c_s[lane] = __fdividef(SV, S) + s_bv[lane];
    }
    // slice-0 blocks zero the other-parity buffer for the NEXT call
    // (visible to next launch via kernel boundary; 64 floats = 16 f4)
    if (slice == 0 && w == 1 && lane < 16) {
        ((float4*)&g_acc[par ^ 1u][b][0][0])[lane] = make_float4(0.f, 0.f, 0.f, 0.f);
    }
    __syncthreads();

    if (tid < Dd) {
        float acc = s_bo[tid];
        #pragma unroll
        for (int h2 = 0; h2 < Hh; h2++)
            acc = fmaf(c_s[h2], wo_s[tid * WPAD + h2], acc);
        y[tid] = acc;
    }
    __syncthreads();

    // 256 f4 = 4KB broadcast output for this slice
    ((float4*)(out + ((size_t)b * Ss + slice * 32) * Dd))[tid] =
        ((const float4*)y)[tid & 7];
}

extern "C" void kernel_launch(void* const* d_in, const int* in_sizes, int n_in,
                              void* d_out, int out_size)
{
    // metadata order: x, Wq, bq, Wk, bk, Wv, bv, Wo, bo
    const float* x  = (const float*)d_in[0];
    const float* Wk = (const float*)d_in[3];
    const float* bk = (const float*)d_in[4];
    const float* Wv = (const float*)d_in[5];
    const float* bv = (const float*)d_in[6];
    const float* Wo = (const float*)d_in[7];
    const float* bo = (const float*)d_in[8];
    float* out = (float*)d_out;

    foaa_fused<<<NBLK, NTHR>>>(x, Wk, bk, Wv, bv, Wo, bo, out);
}